// round 17
// baseline (speedup 1.0000x reference)
#include <cuda_runtime.h>

#define NN 524288
#define ROWS_PB 192
#define GRID ((NN + ROWS_PB - 1) / ROWS_PB)   // 2731
#define DD 64
#define HH 128
#define EE 8
#define AA 18
#define BN_EPS 1e-5f

typedef unsigned long long u64;

__device__ __forceinline__ u64 pk2(float lo, float hi) {
    u64 r; asm("mov.b64 %0,{%1,%2};" : "=l"(r) : "f"(lo), "f"(hi)); return r;
}
__device__ __forceinline__ void upk2(u64 v, float& lo, float& hi) {
    asm("mov.b64 {%0,%1},%2;" : "=f"(lo), "=f"(hi) : "l"(v));
}
__device__ __forceinline__ void ffma2(u64& d, u64 a, u64 b) {
    asm("fma.rn.f32x2 %0,%1,%2,%0;" : "+l"(d) : "l"(a), "l"(b));
}
__device__ __forceinline__ u64 add2(u64 a, u64 b) {
    u64 r; asm("add.rn.f32x2 %0,%1,%2;" : "=l"(r) : "l"(a), "l"(b)); return r;
}

// smem layout (float offsets):
//   w1e [0, 4096)        W1 even u64s: [j][16 u64] (pw[i].x stream)
//   w1o [4104, 8200)     W1 odd  u64s (+32B skew => different banks)
//   w2t [8200, 9224)     W2 transposed [j][8]
//   sbs [9224, 9480)     (scale,bias) per j
//   b2s [9480, 9496)
//   wes [9496, 18712)    We flat [8][18][64] (unpadded)
#define W1E_OFF 0
#define W1O_OFF 4104
#define W2T_OFF 8200
#define SBS_OFF 9224
#define B2S_OFF 9480
#define WES_OFF 9496
#define WE_STRIDE 1152
#define SMEM_FLOATS 18712

__global__ __launch_bounds__(128, 3) void moe_fused(
    const float* __restrict__ X,  const float* __restrict__ W1, const float* __restrict__ b1,
    const float* __restrict__ gamma, const float* __restrict__ beta,
    const float* __restrict__ rmean, const float* __restrict__ rvar,
    const float* __restrict__ W2, const float* __restrict__ b2, const float* __restrict__ We,
    float* __restrict__ out, float* __restrict__ ret)
{
    extern __shared__ float sm[];
    float* w2t = sm + W2T_OFF;
    float* sbs = sm + SBS_OFF;
    float* b2s = sm + B2S_OFF;
    float* wes = sm + WES_OFF;

    const int tid = threadIdx.x;

    // ---- stage W1 deinterleaved (even/odd u64 streams) ----
    {
        const ulonglong2* src = (const ulonglong2*)W1;
        u64* dE = (u64*)(sm + W1E_OFF);
        u64* dO = (u64*)(sm + W1O_OFF);
        #pragma unroll
        for (int it = 0; it < 16; it++) {
            int idx = tid + 128 * it;          // < 2048: j = idx>>4, i = idx&15
            ulonglong2 v = src[idx];
            dE[idx] = v.x;
            dO[idx] = v.y;
        }
    }
    // ---- We flat copy ----
    {
        const float4* src = (const float4*)We;
        float4* dst = (float4*)wes;
        #pragma unroll
        for (int it = 0; it < 18; it++) dst[tid + 128 * it] = src[tid + 128 * it];
    }
    #pragma unroll
    for (int it = 0; it < 8; it++) {
        int idx = tid + 128 * it;
        int j = idx >> 3, e = idx & 7;
        w2t[idx] = W2[e * HH + j];
    }
    {
        int j = tid;
        float s = gamma[j] * rsqrtf(rvar[j] + BN_EPS);
        sbs[2 * j]     = s;
        sbs[2 * j + 1] = s * (b1[j] - rmean[j]) + beta[j];
    }
    if (tid < EE) b2s[tid] = b2[tid];
    __syncthreads();

    const int lane = tid & 31;
    const int warp = tid >> 5;
    const int slot = lane & 15;
    const int p    = lane >> 4;          // accumulator parity (0: a0/even, 1: a1/odd)

    const int row0 = blockIdx.x * ROWS_PB;
    int rowi[3]; bool valid[3];
    #pragma unroll
    for (int rr = 0; rr < 3; rr++) {
        int r = row0 + warp * 48 + rr * 16 + slot;
        valid[rr] = (r < NN);
        rowi[rr] = valid[rr] ? r : (NN - 1);
    }

    // ---- x: parity-selected u64 halves (16 u64 per row) ----
    u64 xe0[16], xe1[16], xe2[16];
    {
        const u64* p0 = (const u64*)(X + (size_t)rowi[0] * DD);
        const u64* p1 = (const u64*)(X + (size_t)rowi[1] * DD);
        const u64* p2 = (const u64*)(X + (size_t)rowi[2] * DD);
        #pragma unroll
        for (int i = 0; i < 16; i++) {
            xe0[i] = p0[2 * i + p];
            xe1[i] = p1[2 * i + p];
            xe2[i] = p2[2 * i + p];
        }
    }

    const u64 Z = pk2(0.f, 0.f);

    // logits: this lane owns experts [4p, 4p+4)
    u64 lg0[2], lg1[2], lg2[2];
    #pragma unroll
    for (int q = 0; q < 2; q++) {
        u64 b2p = pk2(b2s[4 * p + 2 * q], b2s[4 * p + 2 * q + 1]);
        lg0[q] = b2p; lg1[q] = b2p; lg2[q] = b2p;
    }

    const ulonglong2* pwbase = (const ulonglong2*)(sm + (p ? W1O_OFF : W1E_OFF));

    // ---- gating: parity chain per lane; EXACT R6 chain order ----
    #pragma unroll 1
    for (int j = 0; j < HH; j++) {
        const ulonglong2* pw = pwbase + j * 8;   // 16 u64 per j
        u64 A0 = Z, A1 = Z, A2 = Z;
        #pragma unroll
        for (int m = 0; m < 8; m++) {
            ulonglong2 t = pw[m];                // (w_{2m}, w_{2m+1}) of this parity stream
            ffma2(A0, t.x, xe0[2 * m]);
            ffma2(A1, t.x, xe1[2 * m]);
            ffma2(A2, t.x, xe2[2 * m]);
            ffma2(A0, t.y, xe0[2 * m + 1]);
            ffma2(A1, t.y, xe1[2 * m + 1]);
            ffma2(A2, t.y, xe2[2 * m + 1]);
        }
        // exchange with partner lane; both sides compute add2(a0, a1)
        u64 o0 = __shfl_xor_sync(0xffffffffu, A0, 16);
        u64 o1 = __shfl_xor_sync(0xffffffffu, A1, 16);
        u64 o2 = __shfl_xor_sync(0xffffffffu, A2, 16);
        u64 s0 = p ? add2(o0, A0) : add2(A0, o0);
        u64 s1 = p ? add2(o1, A1) : add2(A1, o1);
        u64 s2 = p ? add2(o2, A2) : add2(A2, o2);
        float e0, f0, e1, f1, e2, f2;
        upk2(s0, e0, f0); upk2(s1, e1, f1); upk2(s2, e2, f2);
        float dot0 = e0 + f0, dot1 = e1 + f1, dot2 = e2 + f2;

        float2 sb = ((const float2*)sbs)[j];
        float y0 = fmaxf(fmaf(sb.x, dot0, sb.y), 0.f);
        float y1 = fmaxf(fmaf(sb.x, dot1, sb.y), 0.f);
        float y2 = fmaxf(fmaf(sb.x, dot2, sb.y), 0.f);
        u64 yb0 = pk2(y0, y0), yb1 = pk2(y1, y1), yb2 = pk2(y2, y2);

        ulonglong2 q = *(const ulonglong2*)(w2t + j * EE + p * 4);
        ffma2(lg0[0], q.x, yb0);
        ffma2(lg1[0], q.x, yb1);
        ffma2(lg2[0], q.x, yb2);
        ffma2(lg0[1], q.y, yb0);
        ffma2(lg1[1], q.y, yb1);
        ffma2(lg2[1], q.y, yb2);
    }

    // ---- per row: assemble logits, argmax, one-hot, expert GEMV ----
    #pragma unroll 1
    for (int rr = 0; rr < 3; rr++) {
        if (!valid[rr]) continue;
        const u64* lg = (rr == 0) ? lg0 : (rr == 1) ? lg1 : lg2;
        const int row = rowi[rr];

        u64 q0 = __shfl_xor_sync(0xffffffffu, lg[0], 16);
        u64 q1 = __shfl_xor_sync(0xffffffffu, lg[1], 16);
        float lf[8];
        float a, b;
        upk2(lg[0], a, b); lf[4 * p + 0] = a; lf[4 * p + 1] = b;
        upk2(lg[1], a, b); lf[4 * p + 2] = a; lf[4 * p + 3] = b;
        int ob = (p ^ 1) * 4;
        upk2(q0, a, b); lf[ob + 0] = a; lf[ob + 1] = b;
        upk2(q1, a, b); lf[ob + 2] = a; lf[ob + 3] = b;

        int best = 0; float bv = lf[0];
        #pragma unroll
        for (int e = 1; e < 8; e++) if (lf[e] > bv) { bv = lf[e]; best = e; }

        if (p == 0) {
            float rv[8];
            #pragma unroll
            for (int e = 0; e < 8; e++) rv[e] = (e == best) ? 1.0f : 0.0f;
            float4* pr = (float4*)(ret + (size_t)row * EE);
            pr[0] = make_float4(rv[0], rv[1], rv[2], rv[3]);
            pr[1] = make_float4(rv[4], rv[5], rv[6], rv[7]);
        }

        // expert GEMV: reload full x (L2), lane pair splits A-rows 9/9
        u64 xq[32];
        const ulonglong2* pg = (const ulonglong2*)(X + (size_t)row * DD);
        #pragma unroll
        for (int i = 0; i < 16; i++) {
            ulonglong2 t = pg[i];
            xq[2 * i] = t.x; xq[2 * i + 1] = t.y;
        }

        const ulonglong2* pe = (const ulonglong2*)(wes + best * WE_STRIDE);
        float* orow = out + (size_t)row * AA;
        int aStart = p * 9;
        #pragma unroll
        for (int ai = 0; ai < 9; ai++) {
            int aidx = aStart + ai;
            u64 a0 = Z, a1 = Z, a2 = Z, a3 = Z;
            #pragma unroll
            for (int m = 0; m < 8; m++) {
                ulonglong2 w = pe[aidx * 16 + 2 * m];
                ulonglong2 v = pe[aidx * 16 + 2 * m + 1];
                ffma2(a0, w.x, xq[4 * m + 0]);
                ffma2(a1, w.y, xq[4 * m + 1]);
                ffma2(a2, v.x, xq[4 * m + 2]);
                ffma2(a3, v.y, xq[4 * m + 3]);
            }
            u64 s = add2(add2(a0, a1), add2(a2, a3));
            float lo, hi; upk2(s, lo, hi);
            orow[aidx] = lo + hi;
        }
    }
}

extern "C" void kernel_launch(void* const* d_in, const int* in_sizes, int n_in,
                              void* d_out, int out_size) {
    const float* X     = (const float*)d_in[0];
    const float* W1    = (const float*)d_in[1];
    const float* b1    = (const float*)d_in[2];
    const float* gamma = (const float*)d_in[3];
    const float* beta  = (const float*)d_in[4];
    const float* rmean = (const float*)d_in[5];
    const float* rvar  = (const float*)d_in[6];
    const float* W2    = (const float*)d_in[7];
    const float* b2    = (const float*)d_in[8];
    const float* We    = (const float*)d_in[9];

    float* out = (float*)d_out;                    // [N, A]
    float* ret = out + (size_t)NN * AA;            // [N, E]

    size_t smem = SMEM_FLOATS * sizeof(float);
    static bool attr_set = false;
    if (!attr_set) {
        cudaFuncSetAttribute(moe_fused, cudaFuncAttributeMaxDynamicSharedMemorySize, (int)smem);
        attr_set = true;
    }
    moe_fused<<<GRID, 128, smem>>>(X, W1, b1, gamma, beta, rmean, rvar, W2, b2, We, out, ret);
}